// round 11
// baseline (speedup 1.0000x reference)
#include <cuda_runtime.h>
#include <cuda_bf16.h>
#include <cstdint>

#define LL   2048
#define BB   2
#define DMODEL 512
#define HH   8
#define DKK  64
#define NT   4096   // BB*LL
#define HB   16     // HH*BB

// ---------------- scratch (device globals; no allocation allowed) ----------------
__device__ __nv_bfloat16 g_qhb[HB * LL * DKK];  // [hb][l][d] bf16, pre-scaled 1/64
__device__ __nv_bfloat16 g_khb[HB * LL * DKK];
__device__ __nv_bfloat16 g_vhb[HB * LL * DKK];
__device__ __nv_bfloat16 g_ctxbf[NT * DMODEL];  // ctx bf16 [b*L+l][h*64+d]
__device__ float g_linv[HB * LL];               // 1 / row sumexp

// ---------------- helpers ----------------
__device__ __forceinline__ uint32_t smem_u32(const void* p) {
    uint32_t a;
    asm("{ .reg .u64 t; cvta.to.shared.u64 t, %1; cvt.u32.u64 %0, t; }" : "=r"(a) : "l"(p));
    return a;
}
__device__ __forceinline__ uint32_t bf16x2(float lo, float hi) {
    uint32_t r;
    asm("cvt.rn.bf16x2.f32 %0, %1, %2;" : "=r"(r) : "f"(hi), "f"(lo));
    return r;
}
__device__ __forceinline__ void ldsm4(uint32_t* r, uint32_t addr) {
    asm volatile("ldmatrix.sync.aligned.m8n8.x4.shared.b16 {%0,%1,%2,%3}, [%4];"
                 : "=r"(r[0]), "=r"(r[1]), "=r"(r[2]), "=r"(r[3]) : "r"(addr));
}
__device__ __forceinline__ void ldsm4t(uint32_t* r, uint32_t addr) {
    asm volatile("ldmatrix.sync.aligned.m8n8.x4.trans.shared.b16 {%0,%1,%2,%3}, [%4];"
                 : "=r"(r[0]), "=r"(r[1]), "=r"(r[2]), "=r"(r[3]) : "r"(addr));
}
__device__ __forceinline__ void mma_bf16(float* c, const uint32_t* a, uint32_t b0, uint32_t b1) {
    asm volatile(
        "mma.sync.aligned.m16n8k16.row.col.f32.bf16.bf16.f32 "
        "{%0,%1,%2,%3}, {%4,%5,%6,%7}, {%8,%9}, {%0,%1,%2,%3};"
        : "+f"(c[0]), "+f"(c[1]), "+f"(c[2]), "+f"(c[3])
        : "r"(a[0]), "r"(a[1]), "r"(a[2]), "r"(a[3]), "r"(b0), "r"(b1));
}

// =====================================================================
// Kernel 1: fused QKV projection via bf16 mma.
// CTA: 64 rows x 128 cols, K in chunks of 64. 8 warps, 16m x 64n.
// =====================================================================
__global__ __launch_bounds__(256) void proj_kernel(
    const float* __restrict__ qin, const float* __restrict__ kin, const float* __restrict__ vin,
    const float* __restrict__ Wq, const float* __restrict__ bq,
    const float* __restrict__ Wk, const float* __restrict__ bk,
    const float* __restrict__ Wv, const float* __restrict__ bv)
{
    __shared__ __nv_bfloat16 As[64][72];    // X chunk, [m][k]
    __shared__ __nv_bfloat16 Ws[64][136];   // W chunk, [k][n]

    const int z = blockIdx.z;
    const float* X    = (z == 0) ? qin : (z == 1) ? kin : vin;
    const float* W    = (z == 0) ? Wq  : (z == 1) ? Wk  : Wv;
    const float* bias = (z == 0) ? bq  : (z == 1) ? bk  : bv;
    __nv_bfloat16* outp = (z == 0) ? g_qhb : (z == 1) ? g_khb : g_vhb;
    const float scale = (z == 0) ? (1.0f / 64.0f) : 1.0f;

    const int row0 = blockIdx.y * 64;
    const int col0 = blockIdx.x * 128;
    const int t = threadIdx.x, w = t >> 5, l = t & 31;
    const int qw = (w >> 1) * 16;
    const int nw = (w & 1) * 64;

    float acc[8][4];
#pragma unroll
    for (int nt = 0; nt < 8; nt++)
#pragma unroll
        for (int e = 0; e < 4; e++) acc[nt][e] = 0.0f;

    for (int k0 = 0; k0 < DMODEL; k0 += 64) {
#pragma unroll
        for (int p = 0; p < 4; p++) {
            int fi = t + p * 256;
            int row = fi >> 4, c4 = fi & 15;
            float4 f = *(const float4*)(X + (size_t)(row0 + row) * DMODEL + k0 + c4 * 4);
            uint2 pk = {bf16x2(f.x, f.y), bf16x2(f.z, f.w)};
            *(uint2*)&As[row][c4 * 4] = pk;
        }
#pragma unroll
        for (int p = 0; p < 8; p++) {
            int fi = t + p * 256;
            int krow = fi >> 5, c4 = fi & 31;
            float4 f = *(const float4*)(W + (size_t)(k0 + krow) * DMODEL + col0 + c4 * 4);
            uint2 pk = {bf16x2(f.x, f.y), bf16x2(f.z, f.w)};
            *(uint2*)&Ws[krow][c4 * 4] = pk;
        }
        __syncthreads();

#pragma unroll
        for (int d0 = 0; d0 < 64; d0 += 16) {
            uint32_t a[4];
            ldsm4(a, smem_u32(&As[qw + (l & 15)][d0 + (l >> 4) * 8]));
#pragma unroll
            for (int ntp = 0; ntp < 4; ntp++) {
                uint32_t bfr[4];
                int krow = d0 + (l & 7) + 8 * ((l >> 3) & 1);
                ldsm4t(bfr, smem_u32(&Ws[krow][nw + ntp * 16 + 8 * (l >> 4)]));
                mma_bf16(acc[ntp * 2 + 0], a, bfr[0], bfr[1]);
                mma_bf16(acc[ntp * 2 + 1], a, bfr[2], bfr[3]);
            }
        }
        __syncthreads();
    }

    const int r0 = row0 + qw + (l >> 2);
    const int r1 = r0 + 8;
#pragma unroll
    for (int nt = 0; nt < 8; nt++) {
        int cg = col0 + nw + nt * 8 + (l & 3) * 2;
        int h = cg >> 6, d = cg & 63;
        float b0 = bias[cg], b1 = bias[cg + 1];
        float o00 = (acc[nt][0] + b0) * scale;
        float o01 = (acc[nt][1] + b1) * scale;
        float o10 = (acc[nt][2] + b0) * scale;
        float o11 = (acc[nt][3] + b1) * scale;
        *(uint32_t*)(outp + (size_t)((h * BB + (r0 >> 11)) * LL + (r0 & 2047)) * DKK + d) = bf16x2(o00, o01);
        *(uint32_t*)(outp + (size_t)((h * BB + (r1 >> 11)) * LL + (r1 & 2047)) * DKK + d) = bf16x2(o10, o11);
    }
}

// =====================================================================
// Kernel 2: pass 1 — row sums of exp(S) -> g_linv.
// CTA: 64 q rows, k tiles of 128. 8 warps, 16q x 64k.
// K loads software-pipelined through registers.
// =====================================================================
__global__ __launch_bounds__(256) void linv_kernel(const int* __restrict__ mask)
{
    __shared__ __nv_bfloat16 Qs[64][72];
    __shared__ __nv_bfloat16 Ks[128][72];
    __shared__ float sred[2][64];

    const int hb = blockIdx.y;
    const int q0 = blockIdx.x * 64;
    const int bat = hb & 1;
    const int t = threadIdx.x, w = t >> 5, l = t & 31;
    const int qw = (w >> 1) * 16;
    const int kwsel = w & 1;
    const int kw = kwsel * 64;

    const __nv_bfloat16* qb = g_qhb + (size_t)hb * LL * DKK + (size_t)q0 * DKK;
    const __nv_bfloat16* kb = g_khb + (size_t)hb * LL * DKK;
    const int* mb = mask + (size_t)bat * LL * LL;

    const int srow = t >> 3, sc8 = t & 7;   // staging coords (p-invariant parts)

#pragma unroll
    for (int p = 0; p < 2; p++) {
        int fi = t + p * 256;
        int row = fi >> 3, c8 = fi & 7;
        *(uint4*)&Qs[row][c8 * 8] = *(const uint4*)(qb + (size_t)row * DKK + c8 * 8);
    }

    // prefetch K tile 0 into registers
    uint4 kreg[4];
#pragma unroll
    for (int p = 0; p < 4; p++)
        kreg[p] = *(const uint4*)(kb + (size_t)(srow + p * 32) * DKK + sc8 * 8);

    float rs0 = 0.0f, rs1 = 0.0f;
    const int r0g = q0 + qw + (l >> 2);
    const int r1g = r0g + 8;

    for (int kt = 0; kt < 16; kt++) {
        // store staged regs to smem
#pragma unroll
        for (int p = 0; p < 4; p++)
            *(uint4*)&Ks[srow + p * 32][sc8 * 8] = kreg[p];
        __syncthreads();

        // prefetch next tile while MMAs run
        if (kt < 15) {
            const int kn = (kt + 1) * 128;
#pragma unroll
            for (int p = 0; p < 4; p++)
                kreg[p] = *(const uint4*)(kb + (size_t)(kn + srow + p * 32) * DKK + sc8 * 8);
        }

        float acc[8][4];
#pragma unroll
        for (int nt = 0; nt < 8; nt++)
#pragma unroll
            for (int e = 0; e < 4; e++) acc[nt][e] = 0.0f;

#pragma unroll
        for (int d0 = 0; d0 < 64; d0 += 16) {
            uint32_t a[4];
            ldsm4(a, smem_u32(&Qs[qw + (l & 15)][d0 + (l >> 4) * 8]));
#pragma unroll
            for (int ntp = 0; ntp < 4; ntp++) {
                uint32_t bfr[4];
                int nrow = kw + ntp * 16 + (l & 7) + 8 * (l >> 4);
                ldsm4(bfr, smem_u32(&Ks[nrow][d0 + 8 * ((l >> 3) & 1)]));
                mma_bf16(acc[ntp * 2 + 0], a, bfr[0], bfr[1]);
                mma_bf16(acc[ntp * 2 + 1], a, bfr[2], bfr[3]);
            }
        }

        const int k0 = kt * 128;
#pragma unroll
        for (int nt = 0; nt < 8; nt++) {
            int c = k0 + kw + nt * 8 + (l & 3) * 2;
            int2 m0 = *(const int2*)(mb + (size_t)r0g * LL + c);
            int2 m1 = *(const int2*)(mb + (size_t)r1g * LL + c);
            rs0 += (m0.x ? __expf(acc[nt][0]) : 0.0f) + (m0.y ? __expf(acc[nt][1]) : 0.0f);
            rs1 += (m1.x ? __expf(acc[nt][2]) : 0.0f) + (m1.y ? __expf(acc[nt][3]) : 0.0f);
        }
        __syncthreads();
    }

    rs0 += __shfl_xor_sync(0xffffffffu, rs0, 1);
    rs0 += __shfl_xor_sync(0xffffffffu, rs0, 2);
    rs1 += __shfl_xor_sync(0xffffffffu, rs1, 1);
    rs1 += __shfl_xor_sync(0xffffffffu, rs1, 2);
    if ((l & 3) == 0) {
        sred[kwsel][qw + (l >> 2)]     = rs0;
        sred[kwsel][qw + 8 + (l >> 2)] = rs1;
    }
    __syncthreads();
    if (t < 64)
        g_linv[hb * LL + q0 + t] = 1.0f / (sred[0][t] + sred[1][t]);
}

// =====================================================================
// Kernel 3: pass 2 — recompute S, P = mask*exp(S)*linv (write attn),
// accumulate ctx = P @ V (bf16 out).  K/V loads software-pipelined.
// CTA: 64 q rows. 8 warps. S phase: 16q x 32k; PV phase: 16q x 32d.
// =====================================================================
__global__ __launch_bounds__(256) void pv2_kernel(const int* __restrict__ mask,
                                                  float* __restrict__ attn)
{
    __shared__ __nv_bfloat16 Qs[64][72];
    __shared__ __nv_bfloat16 Ks[64][72];
    __shared__ __nv_bfloat16 Vs[64][72];
    __shared__ __nv_bfloat16 Ps[64][72];

    const int hb = blockIdx.y;
    const int q0 = blockIdx.x * 64;
    const int bat = hb & 1;
    const int h = hb >> 1;
    const int t = threadIdx.x, w = t >> 5, l = t & 31;
    const int qw = (w >> 1) * 16;
    const int kw = (w & 1) * 32;
    const int dw = (w & 1) * 32;

    const __nv_bfloat16* qb = g_qhb + (size_t)hb * LL * DKK + (size_t)q0 * DKK;
    const __nv_bfloat16* kb = g_khb + (size_t)hb * LL * DKK;
    const __nv_bfloat16* vb = g_vhb + (size_t)hb * LL * DKK;
    const int* mb = mask + (size_t)bat * LL * LL;
    float* ab = attn + (size_t)hb * LL * LL;

    const int srow = t >> 3, sc8 = t & 7;

#pragma unroll
    for (int p = 0; p < 2; p++) {
        int fi = t + p * 256;
        int row = fi >> 3, c8 = fi & 7;
        *(uint4*)&Qs[row][c8 * 8] = *(const uint4*)(qb + (size_t)row * DKK + c8 * 8);
    }

    const int r0g = q0 + qw + (l >> 2);
    const int r1g = r0g + 8;
    const float li0 = g_linv[hb * LL + r0g];
    const float li1 = g_linv[hb * LL + r1g];

    // prefetch chunk 0
    uint4 kreg[2], vreg[2];
#pragma unroll
    for (int p = 0; p < 2; p++) {
        kreg[p] = *(const uint4*)(kb + (size_t)(srow + p * 32) * DKK + sc8 * 8);
        vreg[p] = *(const uint4*)(vb + (size_t)(srow + p * 32) * DKK + sc8 * 8);
    }

    float acc_pv[4][4];
#pragma unroll
    for (int nt = 0; nt < 4; nt++)
#pragma unroll
        for (int e = 0; e < 4; e++) acc_pv[nt][e] = 0.0f;

    for (int s = 0; s < 32; s++) {
        const int k0 = s * 64;
        // store staged regs
#pragma unroll
        for (int p = 0; p < 2; p++) {
            *(uint4*)&Ks[srow + p * 32][sc8 * 8] = kreg[p];
            *(uint4*)&Vs[srow + p * 32][sc8 * 8] = vreg[p];
        }
        __syncthreads();

        // prefetch next chunk while S/PV MMAs run
        if (s < 31) {
            const int kn = k0 + 64;
#pragma unroll
            for (int p = 0; p < 2; p++) {
                kreg[p] = *(const uint4*)(kb + (size_t)(kn + srow + p * 32) * DKK + sc8 * 8);
                vreg[p] = *(const uint4*)(vb + (size_t)(kn + srow + p * 32) * DKK + sc8 * 8);
            }
        }

        // S phase: warp computes 16q x 32k
        float acc_s[4][4];
#pragma unroll
        for (int nt = 0; nt < 4; nt++)
#pragma unroll
            for (int e = 0; e < 4; e++) acc_s[nt][e] = 0.0f;

#pragma unroll
        for (int d0 = 0; d0 < 64; d0 += 16) {
            uint32_t a[4];
            ldsm4(a, smem_u32(&Qs[qw + (l & 15)][d0 + (l >> 4) * 8]));
#pragma unroll
            for (int ntp = 0; ntp < 2; ntp++) {
                uint32_t bfr[4];
                int nrow = kw + ntp * 16 + (l & 7) + 8 * (l >> 4);
                ldsm4(bfr, smem_u32(&Ks[nrow][d0 + 8 * ((l >> 3) & 1)]));
                mma_bf16(acc_s[ntp * 2 + 0], a, bfr[0], bfr[1]);
                mma_bf16(acc_s[ntp * 2 + 1], a, bfr[2], bfr[3]);
            }
        }

        // epilogue: P = mask * exp(S) * linv; write attn; stage Ps bf16
#pragma unroll
        for (int nt = 0; nt < 4; nt++) {
            int cl = kw + nt * 8 + (l & 3) * 2;
            int c = k0 + cl;
            int2 m0 = *(const int2*)(mb + (size_t)r0g * LL + c);
            int2 m1 = *(const int2*)(mb + (size_t)r1g * LL + c);
            float p00 = m0.x ? __expf(acc_s[nt][0]) * li0 : 0.0f;
            float p01 = m0.y ? __expf(acc_s[nt][1]) * li0 : 0.0f;
            float p10 = m1.x ? __expf(acc_s[nt][2]) * li1 : 0.0f;
            float p11 = m1.y ? __expf(acc_s[nt][3]) * li1 : 0.0f;
            float2 w0 = {p00, p01}, w1 = {p10, p11};
            *(float2*)(ab + (size_t)r0g * LL + c) = w0;
            *(float2*)(ab + (size_t)r1g * LL + c) = w1;
            *(uint32_t*)&Ps[qw + (l >> 2)][cl]     = bf16x2(p00, p01);
            *(uint32_t*)&Ps[qw + 8 + (l >> 2)][cl] = bf16x2(p10, p11);
        }
        __syncthreads();

        // PV phase: warp accumulates 16q x 32d over this 64-k chunk
#pragma unroll
        for (int kk0 = 0; kk0 < 64; kk0 += 16) {
            uint32_t a[4];
            ldsm4(a, smem_u32(&Ps[qw + (l & 15)][kk0 + (l >> 4) * 8]));
#pragma unroll
            for (int ntp = 0; ntp < 2; ntp++) {
                uint32_t bfr[4];
                int krow = kk0 + (l & 7) + 8 * ((l >> 3) & 1);
                ldsm4t(bfr, smem_u32(&Vs[krow][dw + ntp * 16 + 8 * (l >> 4)]));
                mma_bf16(acc_pv[ntp * 2 + 0], a, bfr[0], bfr[1]);
                mma_bf16(acc_pv[ntp * 2 + 1], a, bfr[2], bfr[3]);
            }
        }
        __syncthreads();
    }

    // ctx epilogue (bf16)
#pragma unroll
    for (int nt = 0; nt < 4; nt++) {
        int c = h * 64 + dw + nt * 8 + (l & 3) * 2;
        *(uint32_t*)(g_ctxbf + (size_t)(bat * LL + r0g) * DMODEL + c) = bf16x2(acc_pv[nt][0], acc_pv[nt][1]);
        *(uint32_t*)(g_ctxbf + (size_t)(bat * LL + r1g) * DMODEL + c) = bf16x2(acc_pv[nt][2], acc_pv[nt][3]);
    }
}

// =====================================================================
// Kernel 4: out = ctx(bf16) @ Wo + bo + residual(q), bf16 mma.
// CTA: 64 rows x 128 cols. grid (4, 64).
// =====================================================================
__global__ __launch_bounds__(256) void outproj_kernel(
    const float* __restrict__ resid, const float* __restrict__ Wo,
    const float* __restrict__ bo, float* __restrict__ out)
{
    __shared__ __nv_bfloat16 As[64][72];
    __shared__ __nv_bfloat16 Ws[64][136];

    const int row0 = blockIdx.y * 64;
    const int col0 = blockIdx.x * 128;
    const int t = threadIdx.x, w = t >> 5, l = t & 31;
    const int qw = (w >> 1) * 16;
    const int nw = (w & 1) * 64;

    float acc[8][4];
#pragma unroll
    for (int nt = 0; nt < 8; nt++)
#pragma unroll
        for (int e = 0; e < 4; e++) acc[nt][e] = 0.0f;

    for (int k0 = 0; k0 < DMODEL; k0 += 64) {
#pragma unroll
        for (int p = 0; p < 2; p++) {
            int fi = t + p * 256;
            int row = fi >> 3, c8 = fi & 7;
            *(uint4*)&As[row][c8 * 8] =
                *(const uint4*)(g_ctxbf + (size_t)(row0 + row) * DMODEL + k0 + c8 * 8);
        }
#pragma unroll
        for (int p = 0; p < 8; p++) {
            int fi = t + p * 256;
            int krow = fi >> 5, c4 = fi & 31;
            float4 f = *(const float4*)(Wo + (size_t)(k0 + krow) * DMODEL + col0 + c4 * 4);
            uint2 pk = {bf16x2(f.x, f.y), bf16x2(f.z, f.w)};
            *(uint2*)&Ws[krow][c4 * 4] = pk;
        }
        __syncthreads();

#pragma unroll
        for (int d0 = 0; d0 < 64; d0 += 16) {
            uint32_t a[4];
            ldsm4(a, smem_u32(&As[qw + (l & 15)][d0 + (l >> 4) * 8]));
#pragma unroll
            for (int ntp = 0; ntp < 4; ntp++) {
                uint32_t bfr[4];
                int krow = d0 + (l & 7) + 8 * ((l >> 3) & 1);
                ldsm4t(bfr, smem_u32(&Ws[krow][nw + ntp * 16 + 8 * (l >> 4)]));
                mma_bf16(acc[ntp * 2 + 0], a, bfr[0], bfr[1]);
                mma_bf16(acc[ntp * 2 + 1], a, bfr[2], bfr[3]);
            }
        }
        __syncthreads();
    }

    const int r0 = row0 + qw + (l >> 2);
    const int r1 = r0 + 8;
#pragma unroll
    for (int nt = 0; nt < 8; nt++) {
        int cg = col0 + nw + nt * 8 + (l & 3) * 2;
        float b0 = bo[cg], b1 = bo[cg + 1];
        float2 x0 = *(const float2*)(resid + (size_t)r0 * DMODEL + cg);
        float2 x1 = *(const float2*)(resid + (size_t)r1 * DMODEL + cg);
        float2 o0 = {acc[nt][0] + b0 + x0.x, acc[nt][1] + b1 + x0.y};
        float2 o1 = {acc[nt][2] + b0 + x1.x, acc[nt][3] + b1 + x1.y};
        *(float2*)(out + (size_t)r0 * DMODEL + cg) = o0;
        *(float2*)(out + (size_t)r1 * DMODEL + cg) = o1;
    }
}

// =====================================================================
extern "C" void kernel_launch(void* const* d_in, const int* in_sizes, int n_in,
                              void* d_out, int out_size)
{
    const float* q    = (const float*)d_in[0];
    const float* k    = (const float*)d_in[1];
    const float* v    = (const float*)d_in[2];
    const int*   mask = (const int*)  d_in[3];
    const float* Wq   = (const float*)d_in[4];
    const float* bq   = (const float*)d_in[5];
    const float* Wk   = (const float*)d_in[6];
    const float* bk   = (const float*)d_in[7];
    const float* Wv   = (const float*)d_in[8];
    const float* bv   = (const float*)d_in[9];
    const float* Wo   = (const float*)d_in[10];
    const float* bo   = (const float*)d_in[11];

    float* out  = (float*)d_out;
    float* attn = out + (size_t)NT * DMODEL;

    proj_kernel<<<dim3(4, 64, 3), 256>>>(q, k, v, Wq, bq, Wk, bk, Wv, bv);
    linv_kernel<<<dim3(32, 16), 256>>>(mask);
    pv2_kernel<<<dim3(32, 16), 256>>>(mask, attn);
    outproj_kernel<<<dim3(4, 64), 256>>>(q, Wo, bo, out);
}

// round 12
// speedup vs baseline: 1.7205x; 1.7205x over previous
#include <cuda_runtime.h>
#include <cuda_bf16.h>
#include <cstdint>

#define LL   2048
#define BB   2
#define DMODEL 512
#define HH   8
#define DKK  64
#define NT   4096   // BB*LL
#define HB   16     // HH*BB

// ---------------- scratch (device globals; no allocation allowed) ----------------
__device__ __nv_bfloat16 g_qhb[HB * LL * DKK];  // [hb][l][d] bf16, pre-scaled 1/64
__device__ __nv_bfloat16 g_khb[HB * LL * DKK];
__device__ __nv_bfloat16 g_vhb[HB * LL * DKK];
__device__ __nv_bfloat16 g_ctxbf[NT * DMODEL];  // ctx bf16 [b*L+l][h*64+d]
__device__ float g_linv[HB * LL];               // 1 / row sumexp
__device__ int g_mask_allones;                  // 1 if mask has no zeros

// ---------------- helpers ----------------
__device__ __forceinline__ uint32_t smem_u32(const void* p) {
    uint32_t a;
    asm("{ .reg .u64 t; cvta.to.shared.u64 t, %1; cvt.u32.u64 %0, t; }" : "=r"(a) : "l"(p));
    return a;
}
__device__ __forceinline__ uint32_t bf16x2(float lo, float hi) {
    uint32_t r;
    asm("cvt.rn.bf16x2.f32 %0, %1, %2;" : "=r"(r) : "f"(hi), "f"(lo));
    return r;
}
__device__ __forceinline__ void ldsm4(uint32_t* r, uint32_t addr) {
    asm volatile("ldmatrix.sync.aligned.m8n8.x4.shared.b16 {%0,%1,%2,%3}, [%4];"
                 : "=r"(r[0]), "=r"(r[1]), "=r"(r[2]), "=r"(r[3]) : "r"(addr));
}
__device__ __forceinline__ void ldsm4t(uint32_t* r, uint32_t addr) {
    asm volatile("ldmatrix.sync.aligned.m8n8.x4.trans.shared.b16 {%0,%1,%2,%3}, [%4];"
                 : "=r"(r[0]), "=r"(r[1]), "=r"(r[2]), "=r"(r[3]) : "r"(addr));
}
__device__ __forceinline__ void mma_bf16(float* c, const uint32_t* a, uint32_t b0, uint32_t b1) {
    asm volatile(
        "mma.sync.aligned.m16n8k16.row.col.f32.bf16.bf16.f32 "
        "{%0,%1,%2,%3}, {%4,%5,%6,%7}, {%8,%9}, {%0,%1,%2,%3};"
        : "+f"(c[0]), "+f"(c[1]), "+f"(c[2]), "+f"(c[3])
        : "r"(a[0]), "r"(a[1]), "r"(a[2]), "r"(a[3]), "r"(b0), "r"(b1));
}

// =====================================================================
// Kernel 0a/0b: mask all-ones pre-scan.
// =====================================================================
__global__ void maskflag_init_kernel() { g_mask_allones = 1; }

__global__ __launch_bounds__(256) void maskscan_kernel(const int* __restrict__ mask)
{
    // 2*2048*2048 ints; grid 2048 x 256 threads x 16 ints each
    size_t base = ((size_t)blockIdx.x * 256 + threadIdx.x) * 16;
    bool ok = true;
#pragma unroll
    for (int i = 0; i < 4; i++) {
        int4 m = *(const int4*)(mask + base + i * 4);
        ok &= (m.x != 0) & (m.y != 0) & (m.z != 0) & (m.w != 0);
    }
    if (!__syncthreads_and((int)ok)) {
        if (threadIdx.x == 0) atomicAnd(&g_mask_allones, 0);
    }
}

// =====================================================================
// Kernel 1: fused QKV projection via bf16 mma.
// CTA: 64 rows x 128 cols, K in chunks of 64. 8 warps, 16m x 64n.
// =====================================================================
__global__ __launch_bounds__(256) void proj_kernel(
    const float* __restrict__ qin, const float* __restrict__ kin, const float* __restrict__ vin,
    const float* __restrict__ Wq, const float* __restrict__ bq,
    const float* __restrict__ Wk, const float* __restrict__ bk,
    const float* __restrict__ Wv, const float* __restrict__ bv)
{
    __shared__ __nv_bfloat16 As[64][72];    // X chunk, [m][k]
    __shared__ __nv_bfloat16 Ws[64][136];   // W chunk, [k][n]

    const int z = blockIdx.z;
    const float* X    = (z == 0) ? qin : (z == 1) ? kin : vin;
    const float* W    = (z == 0) ? Wq  : (z == 1) ? Wk  : Wv;
    const float* bias = (z == 0) ? bq  : (z == 1) ? bk  : bv;
    __nv_bfloat16* outp = (z == 0) ? g_qhb : (z == 1) ? g_khb : g_vhb;
    const float scale = (z == 0) ? (1.0f / 64.0f) : 1.0f;

    const int row0 = blockIdx.y * 64;
    const int col0 = blockIdx.x * 128;
    const int t = threadIdx.x, w = t >> 5, l = t & 31;
    const int qw = (w >> 1) * 16;
    const int nw = (w & 1) * 64;

    float acc[8][4];
#pragma unroll
    for (int nt = 0; nt < 8; nt++)
#pragma unroll
        for (int e = 0; e < 4; e++) acc[nt][e] = 0.0f;

    for (int k0 = 0; k0 < DMODEL; k0 += 64) {
#pragma unroll
        for (int p = 0; p < 4; p++) {
            int fi = t + p * 256;
            int row = fi >> 4, c4 = fi & 15;
            float4 f = *(const float4*)(X + (size_t)(row0 + row) * DMODEL + k0 + c4 * 4);
            uint2 pk = {bf16x2(f.x, f.y), bf16x2(f.z, f.w)};
            *(uint2*)&As[row][c4 * 4] = pk;
        }
#pragma unroll
        for (int p = 0; p < 8; p++) {
            int fi = t + p * 256;
            int krow = fi >> 5, c4 = fi & 31;
            float4 f = *(const float4*)(W + (size_t)(k0 + krow) * DMODEL + col0 + c4 * 4);
            uint2 pk = {bf16x2(f.x, f.y), bf16x2(f.z, f.w)};
            *(uint2*)&Ws[krow][c4 * 4] = pk;
        }
        __syncthreads();

#pragma unroll
        for (int d0 = 0; d0 < 64; d0 += 16) {
            uint32_t a[4];
            ldsm4(a, smem_u32(&As[qw + (l & 15)][d0 + (l >> 4) * 8]));
#pragma unroll
            for (int ntp = 0; ntp < 4; ntp++) {
                uint32_t bfr[4];
                int krow = d0 + (l & 7) + 8 * ((l >> 3) & 1);
                ldsm4t(bfr, smem_u32(&Ws[krow][nw + ntp * 16 + 8 * (l >> 4)]));
                mma_bf16(acc[ntp * 2 + 0], a, bfr[0], bfr[1]);
                mma_bf16(acc[ntp * 2 + 1], a, bfr[2], bfr[3]);
            }
        }
        __syncthreads();
    }

    const int r0 = row0 + qw + (l >> 2);
    const int r1 = r0 + 8;
#pragma unroll
    for (int nt = 0; nt < 8; nt++) {
        int cg = col0 + nw + nt * 8 + (l & 3) * 2;
        int h = cg >> 6, d = cg & 63;
        float b0 = bias[cg], b1 = bias[cg + 1];
        float o00 = (acc[nt][0] + b0) * scale;
        float o01 = (acc[nt][1] + b1) * scale;
        float o10 = (acc[nt][2] + b0) * scale;
        float o11 = (acc[nt][3] + b1) * scale;
        *(uint32_t*)(outp + (size_t)((h * BB + (r0 >> 11)) * LL + (r0 & 2047)) * DKK + d) = bf16x2(o00, o01);
        *(uint32_t*)(outp + (size_t)((h * BB + (r1 >> 11)) * LL + (r1 & 2047)) * DKK + d) = bf16x2(o10, o11);
    }
}

// =====================================================================
// Kernel 2: pass 1 — row sums of exp(S) -> g_linv.
// CTA: 64 q rows, k tiles of 128. 8 warps, 16q x 64k.  (R9 geometry)
// =====================================================================
__global__ __launch_bounds__(256) void linv_kernel(const int* __restrict__ mask)
{
    __shared__ __nv_bfloat16 Qs[64][72];
    __shared__ __nv_bfloat16 Ks[128][72];
    __shared__ float sred[2][64];

    const int hb = blockIdx.y;
    const int q0 = blockIdx.x * 64;
    const int bat = hb & 1;
    const int t = threadIdx.x, w = t >> 5, l = t & 31;
    const int qw = (w >> 1) * 16;
    const int kwsel = w & 1;
    const int kw = kwsel * 64;

    const __nv_bfloat16* qb = g_qhb + (size_t)hb * LL * DKK + (size_t)q0 * DKK;
    const __nv_bfloat16* kb = g_khb + (size_t)hb * LL * DKK;
    const int* mb = mask + (size_t)bat * LL * LL;
    const int allones = g_mask_allones;

#pragma unroll
    for (int p = 0; p < 2; p++) {
        int fi = t + p * 256;
        int row = fi >> 3, c8 = fi & 7;
        *(uint4*)&Qs[row][c8 * 8] = *(const uint4*)(qb + (size_t)row * DKK + c8 * 8);
    }

    float rs0 = 0.0f, rs1 = 0.0f;
    const int r0g = q0 + qw + (l >> 2);
    const int r1g = r0g + 8;

    for (int kt = 0; kt < 16; kt++) {
        const int k0 = kt * 128;
#pragma unroll
        for (int p = 0; p < 4; p++) {
            int fi = t + p * 256;
            int row = fi >> 3, c8 = fi & 7;
            *(uint4*)&Ks[row][c8 * 8] = *(const uint4*)(kb + (size_t)(k0 + row) * DKK + c8 * 8);
        }
        __syncthreads();

        float acc[8][4];
#pragma unroll
        for (int nt = 0; nt < 8; nt++)
#pragma unroll
            for (int e = 0; e < 4; e++) acc[nt][e] = 0.0f;

#pragma unroll
        for (int d0 = 0; d0 < 64; d0 += 16) {
            uint32_t a[4];
            ldsm4(a, smem_u32(&Qs[qw + (l & 15)][d0 + (l >> 4) * 8]));
#pragma unroll
            for (int ntp = 0; ntp < 4; ntp++) {
                uint32_t bfr[4];
                int nrow = kw + ntp * 16 + (l & 7) + 8 * (l >> 4);
                ldsm4(bfr, smem_u32(&Ks[nrow][d0 + 8 * ((l >> 3) & 1)]));
                mma_bf16(acc[ntp * 2 + 0], a, bfr[0], bfr[1]);
                mma_bf16(acc[ntp * 2 + 1], a, bfr[2], bfr[3]);
            }
        }

        if (allones) {
#pragma unroll
            for (int nt = 0; nt < 8; nt++) {
                rs0 += __expf(acc[nt][0]) + __expf(acc[nt][1]);
                rs1 += __expf(acc[nt][2]) + __expf(acc[nt][3]);
            }
        } else {
#pragma unroll
            for (int nt = 0; nt < 8; nt++) {
                int c = k0 + kw + nt * 8 + (l & 3) * 2;
                int2 m0 = *(const int2*)(mb + (size_t)r0g * LL + c);
                int2 m1 = *(const int2*)(mb + (size_t)r1g * LL + c);
                rs0 += (m0.x ? __expf(acc[nt][0]) : 0.0f) + (m0.y ? __expf(acc[nt][1]) : 0.0f);
                rs1 += (m1.x ? __expf(acc[nt][2]) : 0.0f) + (m1.y ? __expf(acc[nt][3]) : 0.0f);
            }
        }
        __syncthreads();
    }

    rs0 += __shfl_xor_sync(0xffffffffu, rs0, 1);
    rs0 += __shfl_xor_sync(0xffffffffu, rs0, 2);
    rs1 += __shfl_xor_sync(0xffffffffu, rs1, 1);
    rs1 += __shfl_xor_sync(0xffffffffu, rs1, 2);
    if ((l & 3) == 0) {
        sred[kwsel][qw + (l >> 2)]     = rs0;
        sred[kwsel][qw + 8 + (l >> 2)] = rs1;
    }
    __syncthreads();
    if (t < 64)
        g_linv[hb * LL + q0 + t] = 1.0f / (sred[0][t] + sred[1][t]);
}

// =====================================================================
// Kernel 3: pass 2 — recompute S, P = mask*exp(S)*linv (write attn),
// accumulate ctx = P @ V (bf16 out).  (R9 geometry)
// =====================================================================
__global__ __launch_bounds__(256) void pv2_kernel(const int* __restrict__ mask,
                                                  float* __restrict__ attn)
{
    __shared__ __nv_bfloat16 Qs[64][72];
    __shared__ __nv_bfloat16 Ks[64][72];
    __shared__ __nv_bfloat16 Vs[64][72];
    __shared__ __nv_bfloat16 Ps[64][72];

    const int hb = blockIdx.y;
    const int q0 = blockIdx.x * 64;
    const int bat = hb & 1;
    const int h = hb >> 1;
    const int t = threadIdx.x, w = t >> 5, l = t & 31;
    const int qw = (w >> 1) * 16;
    const int kw = (w & 1) * 32;
    const int dw = (w & 1) * 32;

    const __nv_bfloat16* qb = g_qhb + (size_t)hb * LL * DKK + (size_t)q0 * DKK;
    const __nv_bfloat16* kb = g_khb + (size_t)hb * LL * DKK;
    const __nv_bfloat16* vb = g_vhb + (size_t)hb * LL * DKK;
    const int* mb = mask + (size_t)bat * LL * LL;
    float* ab = attn + (size_t)hb * LL * LL;
    const int allones = g_mask_allones;

#pragma unroll
    for (int p = 0; p < 2; p++) {
        int fi = t + p * 256;
        int row = fi >> 3, c8 = fi & 7;
        *(uint4*)&Qs[row][c8 * 8] = *(const uint4*)(qb + (size_t)row * DKK + c8 * 8);
    }

    const int r0g = q0 + qw + (l >> 2);
    const int r1g = r0g + 8;
    const float li0 = g_linv[hb * LL + r0g];
    const float li1 = g_linv[hb * LL + r1g];

    float acc_pv[4][4];
#pragma unroll
    for (int nt = 0; nt < 4; nt++)
#pragma unroll
        for (int e = 0; e < 4; e++) acc_pv[nt][e] = 0.0f;

    for (int s = 0; s < 32; s++) {
        const int k0 = s * 64;
#pragma unroll
        for (int p = 0; p < 2; p++) {
            int fi = t + p * 256;
            int row = fi >> 3, c8 = fi & 7;
            *(uint4*)&Ks[row][c8 * 8] = *(const uint4*)(kb + (size_t)(k0 + row) * DKK + c8 * 8);
            *(uint4*)&Vs[row][c8 * 8] = *(const uint4*)(vb + (size_t)(k0 + row) * DKK + c8 * 8);
        }
        __syncthreads();

        // S phase: warp computes 16q x 32k
        float acc_s[4][4];
#pragma unroll
        for (int nt = 0; nt < 4; nt++)
#pragma unroll
            for (int e = 0; e < 4; e++) acc_s[nt][e] = 0.0f;

#pragma unroll
        for (int d0 = 0; d0 < 64; d0 += 16) {
            uint32_t a[4];
            ldsm4(a, smem_u32(&Qs[qw + (l & 15)][d0 + (l >> 4) * 8]));
#pragma unroll
            for (int ntp = 0; ntp < 2; ntp++) {
                uint32_t bfr[4];
                int nrow = kw + ntp * 16 + (l & 7) + 8 * (l >> 4);
                ldsm4(bfr, smem_u32(&Ks[nrow][d0 + 8 * ((l >> 3) & 1)]));
                mma_bf16(acc_s[ntp * 2 + 0], a, bfr[0], bfr[1]);
                mma_bf16(acc_s[ntp * 2 + 1], a, bfr[2], bfr[3]);
            }
        }

        // epilogue: P = mask * exp(S) * linv; write attn; stage Ps bf16
#pragma unroll
        for (int nt = 0; nt < 4; nt++) {
            int cl = kw + nt * 8 + (l & 3) * 2;
            int c = k0 + cl;
            float p00, p01, p10, p11;
            if (allones) {
                p00 = __expf(acc_s[nt][0]) * li0;
                p01 = __expf(acc_s[nt][1]) * li0;
                p10 = __expf(acc_s[nt][2]) * li1;
                p11 = __expf(acc_s[nt][3]) * li1;
            } else {
                int2 m0 = *(const int2*)(mb + (size_t)r0g * LL + c);
                int2 m1 = *(const int2*)(mb + (size_t)r1g * LL + c);
                p00 = m0.x ? __expf(acc_s[nt][0]) * li0 : 0.0f;
                p01 = m0.y ? __expf(acc_s[nt][1]) * li0 : 0.0f;
                p10 = m1.x ? __expf(acc_s[nt][2]) * li1 : 0.0f;
                p11 = m1.y ? __expf(acc_s[nt][3]) * li1 : 0.0f;
            }
            float2 w0 = {p00, p01}, w1 = {p10, p11};
            *(float2*)(ab + (size_t)r0g * LL + c) = w0;
            *(float2*)(ab + (size_t)r1g * LL + c) = w1;
            *(uint32_t*)&Ps[qw + (l >> 2)][cl]     = bf16x2(p00, p01);
            *(uint32_t*)&Ps[qw + 8 + (l >> 2)][cl] = bf16x2(p10, p11);
        }
        __syncthreads();

        // PV phase: warp accumulates 16q x 32d over this 64-k chunk
#pragma unroll
        for (int kk0 = 0; kk0 < 64; kk0 += 16) {
            uint32_t a[4];
            ldsm4(a, smem_u32(&Ps[qw + (l & 15)][kk0 + (l >> 4) * 8]));
#pragma unroll
            for (int ntp = 0; ntp < 2; ntp++) {
                uint32_t bfr[4];
                int krow = kk0 + (l & 7) + 8 * ((l >> 3) & 1);
                ldsm4t(bfr, smem_u32(&Vs[krow][dw + ntp * 16 + 8 * (l >> 4)]));
                mma_bf16(acc_pv[ntp * 2 + 0], a, bfr[0], bfr[1]);
                mma_bf16(acc_pv[ntp * 2 + 1], a, bfr[2], bfr[3]);
            }
        }
        __syncthreads();
    }

    // ctx epilogue (bf16)
#pragma unroll
    for (int nt = 0; nt < 4; nt++) {
        int c = h * 64 + dw + nt * 8 + (l & 3) * 2;
        *(uint32_t*)(g_ctxbf + (size_t)(bat * LL + r0g) * DMODEL + c) = bf16x2(acc_pv[nt][0], acc_pv[nt][1]);
        *(uint32_t*)(g_ctxbf + (size_t)(bat * LL + r1g) * DMODEL + c) = bf16x2(acc_pv[nt][2], acc_pv[nt][3]);
    }
}

// =====================================================================
// Kernel 4: out = ctx(bf16) @ Wo + bo + residual(q), bf16 mma.
// =====================================================================
__global__ __launch_bounds__(256) void outproj_kernel(
    const float* __restrict__ resid, const float* __restrict__ Wo,
    const float* __restrict__ bo, float* __restrict__ out)
{
    __shared__ __nv_bfloat16 As[64][72];
    __shared__ __nv_bfloat16 Ws[64][136];

    const int row0 = blockIdx.y * 64;
    const int col0 = blockIdx.x * 128;
    const int t = threadIdx.x, w = t >> 5, l = t & 31;
    const int qw = (w >> 1) * 16;
    const int nw = (w & 1) * 64;

    float acc[8][4];
#pragma unroll
    for (int nt = 0; nt < 8; nt++)
#pragma unroll
        for (int e = 0; e < 4; e++) acc[nt][e] = 0.0f;

    for (int k0 = 0; k0 < DMODEL; k0 += 64) {
#pragma unroll
        for (int p = 0; p < 2; p++) {
            int fi = t + p * 256;
            int row = fi >> 3, c8 = fi & 7;
            *(uint4*)&As[row][c8 * 8] =
                *(const uint4*)(g_ctxbf + (size_t)(row0 + row) * DMODEL + k0 + c8 * 8);
        }
#pragma unroll
        for (int p = 0; p < 8; p++) {
            int fi = t + p * 256;
            int krow = fi >> 5, c4 = fi & 31;
            float4 f = *(const float4*)(Wo + (size_t)(k0 + krow) * DMODEL + col0 + c4 * 4);
            uint2 pk = {bf16x2(f.x, f.y), bf16x2(f.z, f.w)};
            *(uint2*)&Ws[krow][c4 * 4] = pk;
        }
        __syncthreads();

#pragma unroll
        for (int d0 = 0; d0 < 64; d0 += 16) {
            uint32_t a[4];
            ldsm4(a, smem_u32(&As[qw + (l & 15)][d0 + (l >> 4) * 8]));
#pragma unroll
            for (int ntp = 0; ntp < 4; ntp++) {
                uint32_t bfr[4];
                int krow = d0 + (l & 7) + 8 * ((l >> 3) & 1);
                ldsm4t(bfr, smem_u32(&Ws[krow][nw + ntp * 16 + 8 * (l >> 4)]));
                mma_bf16(acc[ntp * 2 + 0], a, bfr[0], bfr[1]);
                mma_bf16(acc[ntp * 2 + 1], a, bfr[2], bfr[3]);
            }
        }
        __syncthreads();
    }

    const int r0 = row0 + qw + (l >> 2);
    const int r1 = r0 + 8;
#pragma unroll
    for (int nt = 0; nt < 8; nt++) {
        int cg = col0 + nw + nt * 8 + (l & 3) * 2;
        float b0 = bo[cg], b1 = bo[cg + 1];
        float2 x0 = *(const float2*)(resid + (size_t)r0 * DMODEL + cg);
        float2 x1 = *(const float2*)(resid + (size_t)r1 * DMODEL + cg);
        float2 o0 = {acc[nt][0] + b0 + x0.x, acc[nt][1] + b1 + x0.y};
        float2 o1 = {acc[nt][2] + b0 + x1.x, acc[nt][3] + b1 + x1.y};
        *(float2*)(out + (size_t)r0 * DMODEL + cg) = o0;
        *(float2*)(out + (size_t)r1 * DMODEL + cg) = o1;
    }
}

// =====================================================================
extern "C" void kernel_launch(void* const* d_in, const int* in_sizes, int n_in,
                              void* d_out, int out_size)
{
    const float* q    = (const float*)d_in[0];
    const float* k    = (const float*)d_in[1];
    const float* v    = (const float*)d_in[2];
    const int*   mask = (const int*)  d_in[3];
    const float* Wq   = (const float*)d_in[4];
    const float* bq   = (const float*)d_in[5];
    const float* Wk   = (const float*)d_in[6];
    const float* bk   = (const float*)d_in[7];
    const float* Wv   = (const float*)d_in[8];
    const float* bv   = (const float*)d_in[9];
    const float* Wo   = (const float*)d_in[10];
    const float* bo   = (const float*)d_in[11];

    float* out  = (float*)d_out;
    float* attn = out + (size_t)NT * DMODEL;

    maskflag_init_kernel<<<1, 1>>>();
    maskscan_kernel<<<2048, 256>>>(mask);
    proj_kernel<<<dim3(4, 64, 3), 256>>>(q, k, v, Wq, bq, Wk, bk, Wv, bv);
    linv_kernel<<<dim3(32, 16), 256>>>(mask);
    pv2_kernel<<<dim3(32, 16), 256>>>(mask, attn);
    outproj_kernel<<<dim3(4, 64), 256>>>(q, Wo, bo, out);
}

// round 15
// speedup vs baseline: 1.8681x; 1.0858x over previous
#include <cuda_runtime.h>
#include <cuda_bf16.h>
#include <cstdint>

#define LL   2048
#define BB   2
#define DMODEL 512
#define HH   8
#define DKK  64
#define NT   4096   // BB*LL
#define HB   16     // HH*BB

// ---------------- scratch (device globals; no allocation allowed) ----------------
__device__ __nv_bfloat16 g_qhb[HB * LL * DKK];  // [hb][l][d] bf16, pre-scaled 1/64
__device__ __nv_bfloat16 g_khb[HB * LL * DKK];
__device__ __nv_bfloat16 g_vhb[HB * LL * DKK];
__device__ __nv_bfloat16 g_ctxbf[NT * DMODEL];  // ctx bf16 [b*L+l][h*64+d]
__device__ float g_linv[HB * LL];               // 1 / row sumexp
__device__ int g_mask_allones;                  // 1 if mask has no zeros

// ---------------- helpers ----------------
__device__ __forceinline__ uint32_t smem_u32(const void* p) {
    uint32_t a;
    asm("{ .reg .u64 t; cvta.to.shared.u64 t, %1; cvt.u32.u64 %0, t; }" : "=r"(a) : "l"(p));
    return a;
}
__device__ __forceinline__ uint32_t bf16x2(float lo, float hi) {
    uint32_t r;
    asm("cvt.rn.bf16x2.f32 %0, %1, %2;" : "=r"(r) : "f"(hi), "f"(lo));
    return r;
}
__device__ __forceinline__ void ldsm4(uint32_t* r, uint32_t addr) {
    asm volatile("ldmatrix.sync.aligned.m8n8.x4.shared.b16 {%0,%1,%2,%3}, [%4];"
                 : "=r"(r[0]), "=r"(r[1]), "=r"(r[2]), "=r"(r[3]) : "r"(addr));
}
__device__ __forceinline__ void ldsm4t(uint32_t* r, uint32_t addr) {
    asm volatile("ldmatrix.sync.aligned.m8n8.x4.trans.shared.b16 {%0,%1,%2,%3}, [%4];"
                 : "=r"(r[0]), "=r"(r[1]), "=r"(r[2]), "=r"(r[3]) : "r"(addr));
}
__device__ __forceinline__ void mma_bf16(float* c, const uint32_t* a, uint32_t b0, uint32_t b1) {
    asm volatile(
        "mma.sync.aligned.m16n8k16.row.col.f32.bf16.bf16.f32 "
        "{%0,%1,%2,%3}, {%4,%5,%6,%7}, {%8,%9}, {%0,%1,%2,%3};"
        : "+f"(c[0]), "+f"(c[1]), "+f"(c[2]), "+f"(c[3])
        : "r"(a[0]), "r"(a[1]), "r"(a[2]), "r"(a[3]), "r"(b0), "r"(b1));
}
__device__ __forceinline__ void bar_pair(int id) {
    asm volatile("bar.sync %0, 64;" :: "r"(id) : "memory");
}

// =====================================================================
// Kernel 0a/0b: mask all-ones pre-scan.
// =====================================================================
__global__ void maskflag_init_kernel() { g_mask_allones = 1; }

__global__ __launch_bounds__(256) void maskscan_kernel(const int* __restrict__ mask)
{
    size_t base = ((size_t)blockIdx.x * 256 + threadIdx.x) * 16;
    bool ok = true;
#pragma unroll
    for (int i = 0; i < 4; i++) {
        int4 m = *(const int4*)(mask + base + i * 4);
        ok &= (m.x != 0) & (m.y != 0) & (m.z != 0) & (m.w != 0);
    }
    if (!__syncthreads_and((int)ok)) {
        if (threadIdx.x == 0) atomicAnd(&g_mask_allones, 0);
    }
}

// =====================================================================
// Kernel 1: fused QKV projection via bf16 mma.
// =====================================================================
__global__ __launch_bounds__(256) void proj_kernel(
    const float* __restrict__ qin, const float* __restrict__ kin, const float* __restrict__ vin,
    const float* __restrict__ Wq, const float* __restrict__ bq,
    const float* __restrict__ Wk, const float* __restrict__ bk,
    const float* __restrict__ Wv, const float* __restrict__ bv)
{
    __shared__ __nv_bfloat16 As[64][72];
    __shared__ __nv_bfloat16 Ws[64][136];

    const int z = blockIdx.z;
    const float* X    = (z == 0) ? qin : (z == 1) ? kin : vin;
    const float* W    = (z == 0) ? Wq  : (z == 1) ? Wk  : Wv;
    const float* bias = (z == 0) ? bq  : (z == 1) ? bk  : bv;
    __nv_bfloat16* outp = (z == 0) ? g_qhb : (z == 1) ? g_khb : g_vhb;
    const float scale = (z == 0) ? (1.0f / 64.0f) : 1.0f;

    const int row0 = blockIdx.y * 64;
    const int col0 = blockIdx.x * 128;
    const int t = threadIdx.x, w = t >> 5, l = t & 31;
    const int qw = (w >> 1) * 16;
    const int nw = (w & 1) * 64;

    float acc[8][4];
#pragma unroll
    for (int nt = 0; nt < 8; nt++)
#pragma unroll
        for (int e = 0; e < 4; e++) acc[nt][e] = 0.0f;

    for (int k0 = 0; k0 < DMODEL; k0 += 64) {
#pragma unroll
        for (int p = 0; p < 4; p++) {
            int fi = t + p * 256;
            int row = fi >> 4, c4 = fi & 15;
            float4 f = *(const float4*)(X + (size_t)(row0 + row) * DMODEL + k0 + c4 * 4);
            uint2 pk = {bf16x2(f.x, f.y), bf16x2(f.z, f.w)};
            *(uint2*)&As[row][c4 * 4] = pk;
        }
#pragma unroll
        for (int p = 0; p < 8; p++) {
            int fi = t + p * 256;
            int krow = fi >> 5, c4 = fi & 31;
            float4 f = *(const float4*)(W + (size_t)(k0 + krow) * DMODEL + col0 + c4 * 4);
            uint2 pk = {bf16x2(f.x, f.y), bf16x2(f.z, f.w)};
            *(uint2*)&Ws[krow][c4 * 4] = pk;
        }
        __syncthreads();

#pragma unroll
        for (int d0 = 0; d0 < 64; d0 += 16) {
            uint32_t a[4];
            ldsm4(a, smem_u32(&As[qw + (l & 15)][d0 + (l >> 4) * 8]));
#pragma unroll
            for (int ntp = 0; ntp < 4; ntp++) {
                uint32_t bfr[4];
                int krow = d0 + (l & 7) + 8 * ((l >> 3) & 1);
                ldsm4t(bfr, smem_u32(&Ws[krow][nw + ntp * 16 + 8 * (l >> 4)]));
                mma_bf16(acc[ntp * 2 + 0], a, bfr[0], bfr[1]);
                mma_bf16(acc[ntp * 2 + 1], a, bfr[2], bfr[3]);
            }
        }
        __syncthreads();
    }

    const int r0 = row0 + qw + (l >> 2);
    const int r1 = r0 + 8;
#pragma unroll
    for (int nt = 0; nt < 8; nt++) {
        int cg = col0 + nw + nt * 8 + (l & 3) * 2;
        int h = cg >> 6, d = cg & 63;
        float b0 = bias[cg], b1 = bias[cg + 1];
        float o00 = (acc[nt][0] + b0) * scale;
        float o01 = (acc[nt][1] + b1) * scale;
        float o10 = (acc[nt][2] + b0) * scale;
        float o11 = (acc[nt][3] + b1) * scale;
        *(uint32_t*)(outp + (size_t)((h * BB + (r0 >> 11)) * LL + (r0 & 2047)) * DKK + d) = bf16x2(o00, o01);
        *(uint32_t*)(outp + (size_t)((h * BB + (r1 >> 11)) * LL + (r1 & 2047)) * DKK + d) = bf16x2(o10, o11);
    }
}

// =====================================================================
// Kernel 2: pass 1 — row sums of exp(S) -> g_linv.
// CTA: 64 q rows, k tiles of 128. 8 warps, 16q x 64k.
// Q fragments hoisted out of the k loop.
// =====================================================================
__global__ __launch_bounds__(256) void linv_kernel(const int* __restrict__ mask)
{
    __shared__ __nv_bfloat16 Qs[64][72];
    __shared__ __nv_bfloat16 Ks[128][72];
    __shared__ float sred[2][64];

    const int hb = blockIdx.y;
    const int q0 = blockIdx.x * 64;
    const int bat = hb & 1;
    const int t = threadIdx.x, w = t >> 5, l = t & 31;
    const int qw = (w >> 1) * 16;
    const int kwsel = w & 1;
    const int kw = kwsel * 64;

    const __nv_bfloat16* qb = g_qhb + (size_t)hb * LL * DKK + (size_t)q0 * DKK;
    const __nv_bfloat16* kb = g_khb + (size_t)hb * LL * DKK;
    const int* mb = mask + (size_t)bat * LL * LL;
    const int allones = g_mask_allones;

#pragma unroll
    for (int p = 0; p < 2; p++) {
        int fi = t + p * 256;
        int row = fi >> 3, c8 = fi & 7;
        *(uint4*)&Qs[row][c8 * 8] = *(const uint4*)(qb + (size_t)row * DKK + c8 * 8);
    }
    __syncthreads();

    // hoisted Q fragments (loop-invariant)
    uint32_t aq[4][4];
#pragma unroll
    for (int d0i = 0; d0i < 4; d0i++)
        ldsm4(aq[d0i], smem_u32(&Qs[qw + (l & 15)][d0i * 16 + (l >> 4) * 8]));

    float rs0 = 0.0f, rs1 = 0.0f;
    const int r0g = q0 + qw + (l >> 2);
    const int r1g = r0g + 8;

    for (int kt = 0; kt < 16; kt++) {
        const int k0 = kt * 128;
#pragma unroll
        for (int p = 0; p < 4; p++) {
            int fi = t + p * 256;
            int row = fi >> 3, c8 = fi & 7;
            *(uint4*)&Ks[row][c8 * 8] = *(const uint4*)(kb + (size_t)(k0 + row) * DKK + c8 * 8);
        }
        __syncthreads();

        float acc[8][4];
#pragma unroll
        for (int nt = 0; nt < 8; nt++)
#pragma unroll
            for (int e = 0; e < 4; e++) acc[nt][e] = 0.0f;

#pragma unroll
        for (int d0i = 0; d0i < 4; d0i++) {
            const int d0 = d0i * 16;
#pragma unroll
            for (int ntp = 0; ntp < 4; ntp++) {
                uint32_t bfr[4];
                int nrow = kw + ntp * 16 + (l & 7) + 8 * (l >> 4);
                ldsm4(bfr, smem_u32(&Ks[nrow][d0 + 8 * ((l >> 3) & 1)]));
                mma_bf16(acc[ntp * 2 + 0], aq[d0i], bfr[0], bfr[1]);
                mma_bf16(acc[ntp * 2 + 1], aq[d0i], bfr[2], bfr[3]);
            }
        }

        if (allones) {
#pragma unroll
            for (int nt = 0; nt < 8; nt++) {
                rs0 += __expf(acc[nt][0]) + __expf(acc[nt][1]);
                rs1 += __expf(acc[nt][2]) + __expf(acc[nt][3]);
            }
        } else {
#pragma unroll
            for (int nt = 0; nt < 8; nt++) {
                int c = k0 + kw + nt * 8 + (l & 3) * 2;
                int2 m0 = *(const int2*)(mb + (size_t)r0g * LL + c);
                int2 m1 = *(const int2*)(mb + (size_t)r1g * LL + c);
                rs0 += (m0.x ? __expf(acc[nt][0]) : 0.0f) + (m0.y ? __expf(acc[nt][1]) : 0.0f);
                rs1 += (m1.x ? __expf(acc[nt][2]) : 0.0f) + (m1.y ? __expf(acc[nt][3]) : 0.0f);
            }
        }
        __syncthreads();
    }

    rs0 += __shfl_xor_sync(0xffffffffu, rs0, 1);
    rs0 += __shfl_xor_sync(0xffffffffu, rs0, 2);
    rs1 += __shfl_xor_sync(0xffffffffu, rs1, 1);
    rs1 += __shfl_xor_sync(0xffffffffu, rs1, 2);
    if ((l & 3) == 0) {
        sred[kwsel][qw + (l >> 2)]     = rs0;
        sred[kwsel][qw + 8 + (l >> 2)] = rs1;
    }
    __syncthreads();
    if (t < 64)
        g_linv[hb * LL + q0 + t] = 1.0f / (sred[0][t] + sred[1][t]);
}

// =====================================================================
// Kernel 3: pass 2 — recompute S, P = mask*exp(S)*linv (streamed write),
// accumulate ctx = P @ V (bf16 out).
// Q fragments hoisted; middle barrier is per warp-pair (Ps is pair-local).
// =====================================================================
__global__ __launch_bounds__(256) void pv2_kernel(const int* __restrict__ mask,
                                                  float* __restrict__ attn)
{
    __shared__ __nv_bfloat16 Qs[64][72];
    __shared__ __nv_bfloat16 Ks[64][72];
    __shared__ __nv_bfloat16 Vs[64][72];
    __shared__ __nv_bfloat16 Ps[64][72];

    const int hb = blockIdx.y;
    const int q0 = blockIdx.x * 64;
    const int bat = hb & 1;
    const int h = hb >> 1;
    const int t = threadIdx.x, w = t >> 5, l = t & 31;
    const int qw = (w >> 1) * 16;
    const int kw = (w & 1) * 32;
    const int dw = (w & 1) * 32;
    const int pairid = (w >> 1) + 1;   // named barrier 1..4

    const __nv_bfloat16* qb = g_qhb + (size_t)hb * LL * DKK + (size_t)q0 * DKK;
    const __nv_bfloat16* kb = g_khb + (size_t)hb * LL * DKK;
    const __nv_bfloat16* vb = g_vhb + (size_t)hb * LL * DKK;
    const int* mb = mask + (size_t)bat * LL * LL;
    float* ab = attn + (size_t)hb * LL * LL;
    const int allones = g_mask_allones;

#pragma unroll
    for (int p = 0; p < 2; p++) {
        int fi = t + p * 256;
        int row = fi >> 3, c8 = fi & 7;
        *(uint4*)&Qs[row][c8 * 8] = *(const uint4*)(qb + (size_t)row * DKK + c8 * 8);
    }
    __syncthreads();

    // hoisted Q fragments
    uint32_t aq[4][4];
#pragma unroll
    for (int d0i = 0; d0i < 4; d0i++)
        ldsm4(aq[d0i], smem_u32(&Qs[qw + (l & 15)][d0i * 16 + (l >> 4) * 8]));

    const int r0g = q0 + qw + (l >> 2);
    const int r1g = r0g + 8;
    const float li0 = g_linv[hb * LL + r0g];
    const float li1 = g_linv[hb * LL + r1g];
    float* abr0 = ab + (size_t)r0g * LL;
    float* abr1 = ab + (size_t)r1g * LL;

    float acc_pv[4][4];
#pragma unroll
    for (int nt = 0; nt < 4; nt++)
#pragma unroll
        for (int e = 0; e < 4; e++) acc_pv[nt][e] = 0.0f;

    for (int s = 0; s < 32; s++) {
        const int k0 = s * 64;
#pragma unroll
        for (int p = 0; p < 2; p++) {
            int fi = t + p * 256;
            int row = fi >> 3, c8 = fi & 7;
            *(uint4*)&Ks[row][c8 * 8] = *(const uint4*)(kb + (size_t)(k0 + row) * DKK + c8 * 8);
            *(uint4*)&Vs[row][c8 * 8] = *(const uint4*)(vb + (size_t)(k0 + row) * DKK + c8 * 8);
        }
        __syncthreads();

        // S phase: warp computes 16q x 32k
        float acc_s[4][4];
#pragma unroll
        for (int nt = 0; nt < 4; nt++)
#pragma unroll
            for (int e = 0; e < 4; e++) acc_s[nt][e] = 0.0f;

#pragma unroll
        for (int d0i = 0; d0i < 4; d0i++) {
            const int d0 = d0i * 16;
#pragma unroll
            for (int ntp = 0; ntp < 2; ntp++) {
                uint32_t bfr[4];
                int nrow = kw + ntp * 16 + (l & 7) + 8 * (l >> 4);
                ldsm4(bfr, smem_u32(&Ks[nrow][d0 + 8 * ((l >> 3) & 1)]));
                mma_bf16(acc_s[ntp * 2 + 0], aq[d0i], bfr[0], bfr[1]);
                mma_bf16(acc_s[ntp * 2 + 1], aq[d0i], bfr[2], bfr[3]);
            }
        }

        // epilogue: P = mask * exp(S) * linv; streamed write; stage Ps bf16
#pragma unroll
        for (int nt = 0; nt < 4; nt++) {
            int cl = kw + nt * 8 + (l & 3) * 2;
            int c = k0 + cl;
            float p00, p01, p10, p11;
            if (allones) {
                p00 = __expf(acc_s[nt][0]) * li0;
                p01 = __expf(acc_s[nt][1]) * li0;
                p10 = __expf(acc_s[nt][2]) * li1;
                p11 = __expf(acc_s[nt][3]) * li1;
            } else {
                int2 m0 = *(const int2*)(mb + (size_t)r0g * LL + c);
                int2 m1 = *(const int2*)(mb + (size_t)r1g * LL + c);
                p00 = m0.x ? __expf(acc_s[nt][0]) * li0 : 0.0f;
                p01 = m0.y ? __expf(acc_s[nt][1]) * li0 : 0.0f;
                p10 = m1.x ? __expf(acc_s[nt][2]) * li1 : 0.0f;
                p11 = m1.y ? __expf(acc_s[nt][3]) * li1 : 0.0f;
            }
            float2 w0 = {p00, p01}, w1 = {p10, p11};
            __stcs((float2*)(abr0 + c), w0);
            __stcs((float2*)(abr1 + c), w1);
            *(uint32_t*)&Ps[qw + (l >> 2)][cl]     = bf16x2(p00, p01);
            *(uint32_t*)&Ps[qw + 8 + (l >> 2)][cl] = bf16x2(p10, p11);
        }
        bar_pair(pairid);   // Ps is pair-local: only sync the 2 warps sharing qw

        // PV phase: warp accumulates 16q x 32d over this 64-k chunk
#pragma unroll
        for (int kk0 = 0; kk0 < 64; kk0 += 16) {
            uint32_t a[4];
            ldsm4(a, smem_u32(&Ps[qw + (l & 15)][kk0 + (l >> 4) * 8]));
#pragma unroll
            for (int ntp = 0; ntp < 2; ntp++) {
                uint32_t bfr[4];
                int krow = kk0 + (l & 7) + 8 * ((l >> 3) & 1);
                ldsm4t(bfr, smem_u32(&Vs[krow][dw + ntp * 16 + 8 * (l >> 4)]));
                mma_bf16(acc_pv[ntp * 2 + 0], a, bfr[0], bfr[1]);
                mma_bf16(acc_pv[ntp * 2 + 1], a, bfr[2], bfr[3]);
            }
        }
        __syncthreads();
    }

    // ctx epilogue (bf16)
#pragma unroll
    for (int nt = 0; nt < 4; nt++) {
        int c = h * 64 + dw + nt * 8 + (l & 3) * 2;
        *(uint32_t*)(g_ctxbf + (size_t)(bat * LL + r0g) * DMODEL + c) = bf16x2(acc_pv[nt][0], acc_pv[nt][1]);
        *(uint32_t*)(g_ctxbf + (size_t)(bat * LL + r1g) * DMODEL + c) = bf16x2(acc_pv[nt][2], acc_pv[nt][3]);
    }
}

// =====================================================================
// Kernel 4: out = ctx(bf16) @ Wo + bo + residual(q), bf16 mma.
// =====================================================================
__global__ __launch_bounds__(256) void outproj_kernel(
    const float* __restrict__ resid, const float* __restrict__ Wo,
    const float* __restrict__ bo, float* __restrict__ out)
{
    __shared__ __nv_bfloat16 As[64][72];
    __shared__ __nv_bfloat16 Ws[64][136];

    const int row0 = blockIdx.y * 64;
    const int col0 = blockIdx.x * 128;
    const int t = threadIdx.x, w = t >> 5, l = t & 31;
    const int qw = (w >> 1) * 16;
    const int nw = (w & 1) * 64;

    float acc[8][4];
#pragma unroll
    for (int nt = 0; nt < 8; nt++)
#pragma unroll
        for (int e = 0; e < 4; e++) acc[nt][e] = 0.0f;

    for (int k0 = 0; k0 < DMODEL; k0 += 64) {
#pragma unroll
        for (int p = 0; p < 2; p++) {
            int fi = t + p * 256;
            int row = fi >> 3, c8 = fi & 7;
            *(uint4*)&As[row][c8 * 8] =
                *(const uint4*)(g_ctxbf + (size_t)(row0 + row) * DMODEL + k0 + c8 * 8);
        }
#pragma unroll
        for (int p = 0; p < 8; p++) {
            int fi = t + p * 256;
            int krow = fi >> 5, c4 = fi & 31;
            float4 f = *(const float4*)(Wo + (size_t)(k0 + krow) * DMODEL + col0 + c4 * 4);
            uint2 pk = {bf16x2(f.x, f.y), bf16x2(f.z, f.w)};
            *(uint2*)&Ws[krow][c4 * 4] = pk;
        }
        __syncthreads();

#pragma unroll
        for (int d0 = 0; d0 < 64; d0 += 16) {
            uint32_t a[4];
            ldsm4(a, smem_u32(&As[qw + (l & 15)][d0 + (l >> 4) * 8]));
#pragma unroll
            for (int ntp = 0; ntp < 4; ntp++) {
                uint32_t bfr[4];
                int krow = d0 + (l & 7) + 8 * ((l >> 3) & 1);
                ldsm4t(bfr, smem_u32(&Ws[krow][nw + ntp * 16 + 8 * (l >> 4)]));
                mma_bf16(acc[ntp * 2 + 0], a, bfr[0], bfr[1]);
                mma_bf16(acc[ntp * 2 + 1], a, bfr[2], bfr[3]);
            }
        }
        __syncthreads();
    }

    const int r0 = row0 + qw + (l >> 2);
    const int r1 = r0 + 8;
#pragma unroll
    for (int nt = 0; nt < 8; nt++) {
        int cg = col0 + nw + nt * 8 + (l & 3) * 2;
        float b0 = bo[cg], b1 = bo[cg + 1];
        float2 x0 = *(const float2*)(resid + (size_t)r0 * DMODEL + cg);
        float2 x1 = *(const float2*)(resid + (size_t)r1 * DMODEL + cg);
        float2 o0 = {acc[nt][0] + b0 + x0.x, acc[nt][1] + b1 + x0.y};
        float2 o1 = {acc[nt][2] + b0 + x1.x, acc[nt][3] + b1 + x1.y};
        *(float2*)(out + (size_t)r0 * DMODEL + cg) = o0;
        *(float2*)(out + (size_t)r1 * DMODEL + cg) = o1;
    }
}

// =====================================================================
extern "C" void kernel_launch(void* const* d_in, const int* in_sizes, int n_in,
                              void* d_out, int out_size)
{
    const float* q    = (const float*)d_in[0];
    const float* k    = (const float*)d_in[1];
    const float* v    = (const float*)d_in[2];
    const int*   mask = (const int*)  d_in[3];
    const float* Wq   = (const float*)d_in[4];
    const float* bq   = (const float*)d_in[5];
    const float* Wk   = (const float*)d_in[6];
    const float* bk   = (const float*)d_in[7];
    const float* Wv   = (const float*)d_in[8];
    const float* bv   = (const float*)d_in[9];
    const float* Wo   = (const float*)d_in[10];
    const float* bo   = (const float*)d_in[11];

    float* out  = (float*)d_out;
    float* attn = out + (size_t)NT * DMODEL;

    maskflag_init_kernel<<<1, 1>>>();
    maskscan_kernel<<<2048, 256>>>(mask);
    proj_kernel<<<dim3(4, 64, 3), 256>>>(q, k, v, Wq, bq, Wk, bk, Wv, bv);
    linv_kernel<<<dim3(32, 16), 256>>>(mask);
    pv2_kernel<<<dim3(32, 16), 256>>>(mask, attn);
    outproj_kernel<<<dim3(4, 64), 256>>>(q, Wo, bo, out);
}